// round 13
// baseline (speedup 1.0000x reference)
#include <cuda_runtime.h>
#include <cstdint>

// Binarized NAND-conv net. Warp-autonomous (8 images/warp), 4 threads/image.
// 64-THREAD BLOCKS, __launch_bounds__(64,12): reg ceiling 85 >= ~80 demand
// (no spill), 24 warps/SM, grid 2048 on 1776 slots -> fine-grained wave
// streaming (tail ~4% instead of ~14%).
//  L0: 1x28x28 ->16x14x14 (T=4, arithmetic 2-of-4 majority)  L1: ->16x7x7
//  L2: ->16x6x6  L3: ->16x3x3  L4: ->16x1x1 (T=64)  L5: ->10 (T=16)
//  bit=1 <=> +1 ; out bit = (#mismatch >= T/2).

#define NTHREADS 64
#define NWARPS 2
#define IMGS_PER_WARP 8
#define IMGS_PER_BLOCK 16
#define WPW 196                        // sbits words per warp
#define NWORDS (NWARPS * WPW)          // 392
#define S1 53
#define S2 37
#define S3 13
#define FULL 0xFFFFFFFFu

__device__ __forceinline__ uint32_t nand16(uint64_t a, const uint64_t (&W)[16]) {
    const uint32_t al = (uint32_t)a, ah = (uint32_t)(a >> 32);
    uint32_t acc = 0;
#pragma unroll
    for (int oc = 0; oc < 16; oc++) {
        uint32_t xl = al ^ (uint32_t)W[oc];
        uint32_t xh = ah ^ (uint32_t)(W[oc] >> 32);
        uint32_t D = __popc(xl) + __popc(xh) + 32;
        acc |= (D >> 6) << oc;        // 1 iff mismatches >= 32 (D in [32,96])
    }
    return acc;
}

// L0 cell: 2x2 patch (rows rA,rB, cols cc,cc+1) vs all 16 channels at once.
// Returns 16-bit channel vector (upper bits garbage): (#mismatch >= 2).
__device__ __forceinline__ uint32_t cell16(uint32_t rA, uint32_t rB, int cc,
                                           uint32_t W00, uint32_t W01,
                                           uint32_t W02, uint32_t W03) {
    uint32_t m0 = W00 ^ (uint32_t)(((int)(rA << (31 - cc))) >> 31);
    uint32_t m1 = W01 ^ (uint32_t)(((int)(rA << (30 - cc))) >> 31);
    uint32_t m2 = W02 ^ (uint32_t)(((int)(rB << (31 - cc))) >> 31);
    uint32_t m3 = W03 ^ (uint32_t)(((int)(rB << (30 - cc))) >> 31);
    return (m0 & m1) | (m2 & m3) | ((m0 ^ m1) & (m2 ^ m3));
}

__global__ void __launch_bounds__(NTHREADS, 12)
bnn_mnist_kernel(const float* __restrict__ x,
                 const float* __restrict__ w0, const float* __restrict__ w1,
                 const float* __restrict__ w2, const float* __restrict__ w3,
                 const float* __restrict__ w4, const float* __restrict__ w5,
                 float* __restrict__ out, int B)
{
    __shared__ uint32_t sbits[NWORDS + 1];
    __shared__ uint64_t sw_sh[4][16];
    __shared__ uint32_t sw0t[4];
    __shared__ uint32_t sw5s[10];
    __shared__ uint32_t sact1[IMGS_PER_BLOCK * S1];
    __shared__ uint32_t sact2[IMGS_PER_BLOCK * S2];
    __shared__ uint32_t sact3[IMGS_PER_BLOCK * S3];

    const int tid  = threadIdx.x;
    const int lane = tid & 31;
    const int warp = tid >> 5;
    const int b0 = blockIdx.x * IMGS_PER_BLOCK;

    // ---- weight prep: 64 threads cover layer weights; small tables reuse low tids ----
    {
        int L = tid >> 4, oc = tid & 15;
        const float* wp = (L == 0 ? w1 : L == 1 ? w2 : L == 2 ? w3 : w4) + oc * 64;
        uint64_t v = 0;
#pragma unroll
        for (int ic = 0; ic < 16; ic++)
#pragma unroll
            for (int tap = 0; tap < 4; tap++)
                if (wp[ic * 4 + tap] > 0.0f) v |= 1ull << (tap * 16 + ic);
        sw_sh[L][oc] = v;
    }
    if (tid < 4) {
        uint32_t v = 0;
#pragma unroll
        for (int c = 0; c < 16; c++)
            if (w0[c * 4 + tid] > 0.0f) v |= 1u << c;
        sw0t[tid] = v;
    }
    if (tid < 10) {
        uint32_t v = 0;
#pragma unroll
        for (int ic = 0; ic < 16; ic++)
            if (w5[tid * 16 + ic] > 0.0f) v |= 1u << ic;
        sw5s[tid] = v;
    }
    if (tid == 0) sbits[NWORDS] = 0;
    __syncthreads();

    // ---- warp-autonomous load + binarize + pack (8 images/warp, MLP-7) ----
    {
        const float* chunk = x + (size_t)b0 * 784 + warp * (IMGS_PER_WARP * 784);
        const int sb = warp * WPW;
        if (b0 + IMGS_PER_BLOCK <= B) {
            const float4* c4 = (const float4*)chunk;
#pragma unroll
            for (int c0 = 0; c0 < 49; c0 += 7) {
                float4 v[7];
#pragma unroll
                for (int u = 0; u < 7; u++)
                    v[u] = c4[(c0 + u) * 32 + lane];
#pragma unroll
                for (int u = 0; u < 7; u++) {
                    uint32_t nib = (uint32_t)(v[u].x > 0.0f) | ((uint32_t)(v[u].y > 0.0f) << 1)
                                 | ((uint32_t)(v[u].z > 0.0f) << 2) | ((uint32_t)(v[u].w > 0.0f) << 3);
                    uint32_t val = nib << (4 * (lane & 7));
                    val |= __shfl_xor_sync(FULL, val, 1);
                    val |= __shfl_xor_sync(FULL, val, 2);
                    val |= __shfl_xor_sync(FULL, val, 4);
                    if ((lane & 7) == 0) sbits[sb + (c0 + u) * 4 + (lane >> 3)] = val;
                }
            }
        } else {
            const int nfl = max(min(IMGS_PER_BLOCK, B - b0), 0) * 784 - warp * (IMGS_PER_WARP * 784);
            for (int wdx = 0; wdx < WPW; wdx++) {
                int f = wdx * 32 + lane;
                float v = (f < nfl) ? chunk[f] : 0.0f;
                unsigned bb = __ballot_sync(FULL, v > 0.0f);
                if (lane == 0) sbits[sb + wdx] = bb;
            }
        }
    }
    __syncwarp();

    const int sub  = tid & 3;
    const int limg = tid >> 2;             // 0..15 block-local image
    const int img  = b0 + limg;
    const int bitbase = limg * 784;
    const int row1 = limg * S1;
    const int row2 = limg * S2;
    const int row3 = limg * S3;

    const uint32_t W00 = sw0t[0], W01 = sw0t[1], W02 = sw0t[2], W03 = sw0t[3];

    uint64_t W[16];

    // ---- L0+L1: rows dealt {0,4},{1,5},{2,6},{3} ----
#pragma unroll
    for (int k = 0; k < 16; k++) W[k] = sw_sh[0][k];
#pragma unroll
    for (int t = 0; t < 2; t++) {
        const int i = sub + 4 * t;
        if (i < 7) {
            const int r0 = bitbase + 112 * i;
            int bp = r0;
            uint32_t rA0 = __funnelshift_r(sbits[bp >> 5], sbits[(bp >> 5) + 1], bp);
            bp = r0 + 28;
            uint32_t rB0 = __funnelshift_r(sbits[bp >> 5], sbits[(bp >> 5) + 1], bp);
            bp = r0 + 56;
            uint32_t rA1 = __funnelshift_r(sbits[bp >> 5], sbits[(bp >> 5) + 1], bp);
            bp = r0 + 84;
            uint32_t rB1 = __funnelshift_r(sbits[bp >> 5], sbits[(bp >> 5) + 1], bp);
#pragma unroll
            for (int j = 0; j < 7; j++) {
                const int cc = 4 * j;
                uint32_t v00 = cell16(rA0, rB0, cc,     W00, W01, W02, W03) & 0xFFFFu;
                uint32_t v01 = cell16(rA0, rB0, cc + 2, W00, W01, W02, W03) & 0xFFFFu;
                uint32_t v10 = cell16(rA1, rB1, cc,     W00, W01, W02, W03) & 0xFFFFu;
                uint32_t v11 = cell16(rA1, rB1, cc + 2, W00, W01, W02, W03) & 0xFFFFu;
                uint64_t a64 = (uint64_t)(v00 | (v01 << 16))
                             | ((uint64_t)(v10 | (v11 << 16)) << 32);
                sact1[row1 + i * 7 + j] = nand16(a64, W);
            }
        }
    }
    __syncwarp();

    // ---- L2: 7x7 -> 6x6; p = sub + 4k (exact cover of 36) ----
#pragma unroll
    for (int k = 0; k < 16; k++) W[k] = sw_sh[1][k];
#pragma unroll
    for (int k = 0; k < 9; k++) {
        const int p = sub + 4 * k;
        const int i = p / 6;
        const int q = row1 + p + i;
        uint64_t a64 = (uint64_t)sact1[q] | ((uint64_t)sact1[q + 1] << 16)
                     | ((uint64_t)sact1[q + 7] << 32) | ((uint64_t)sact1[q + 8] << 48);
        sact2[row2 + p] = nand16(a64, W);
    }
    __syncwarp();

    // ---- L3: 6x6 -> 3x3; p = sub + 4k, guard p<9 ----
#pragma unroll
    for (int k = 0; k < 16; k++) W[k] = sw_sh[2][k];
#pragma unroll
    for (int k = 0; k < 3; k++) {
        const int p = sub + 4 * k;
        if (p < 9) {
            const int i = p / 3;
            const int j = p - 3 * i;
            const int q = row2 + 12 * i + 2 * j;
            uint64_t a64 = (uint64_t)sact2[q] | ((uint64_t)sact2[q + 1] << 16)
                         | ((uint64_t)sact2[q + 6] << 32) | ((uint64_t)sact2[q + 7] << 48);
            sact3[row3 + p] = nand16(a64, W);
        }
    }
    __syncwarp();

    // ---- L4: 4 ocs per sub, merge via shfl_xor OR (subs are adjacent lanes) ----
    uint32_t act4;
    {
        uint64_t a4 = (uint64_t)sact3[row3 + 0] | ((uint64_t)sact3[row3 + 1] << 16)
                    | ((uint64_t)sact3[row3 + 3] << 32) | ((uint64_t)sact3[row3 + 4] << 48);
        uint32_t acc = 0;
#pragma unroll
        for (int m = 0; m < 4; m++) {
            const int oc = sub * 4 + m;
            uint64_t xx = a4 ^ sw_sh[3][oc];
            uint32_t D = __popc((uint32_t)xx) + __popc((uint32_t)(xx >> 32)) + 32;
            acc |= (D >> 6) << oc;
        }
        acc |= __shfl_xor_sync(FULL, acc, 1);
        acc |= __shfl_xor_sync(FULL, acc, 2);
        act4 = acc;
    }

    // ---- L5: classes dealt per sub ----
    if (img < B) {
        float* o = out + (size_t)img * 10;
#pragma unroll
        for (int k = 0; k < 3; k++) {
            const int oc = sub + 4 * k;
            if (oc < 10) {
                uint32_t D = __popc((act4 ^ sw5s[oc]) & 0xFFFFu);
                o[oc] = (D >= 8) ? 1.0f : -1.0f;
            }
        }
    }
}

extern "C" void kernel_launch(void* const* d_in, const int* in_sizes, int n_in,
                              void* d_out, int out_size)
{
    const float* x  = (const float*)d_in[0];
    const float* w0 = (const float*)d_in[1];
    const float* w1 = (const float*)d_in[2];
    const float* w2 = (const float*)d_in[3];
    const float* w3 = (const float*)d_in[4];
    const float* w4 = (const float*)d_in[5];
    const float* w5 = (const float*)d_in[6];
    float* out = (float*)d_out;

    int B = in_sizes[0] / 784;
    int grid = (B + IMGS_PER_BLOCK - 1) / IMGS_PER_BLOCK;
    bnn_mnist_kernel<<<grid, NTHREADS>>>(x, w0, w1, w2, w3, w4, w5, out, B);
}

// round 14
// speedup vs baseline: 1.4088x; 1.4088x over previous
#include <cuda_runtime.h>
#include <cstdint>

// Binarized NAND-conv net. Warp-autonomous (8 images/warp), 4 threads/image,
// 256-thread blocks. KEY CHANGE vs best (R9): weights are read from SHARED
// MEMORY inside nand16 (uniform-address LDS.64 broadcast) instead of being
// preloaded into a 32-register array -> true register demand ~50 -> 4 blocks
// per SM (32 warps) WITHOUT spills.
//  L0: 1x28x28 ->16x14x14 (T=4, arithmetic 2-of-4 majority)  L1: ->16x7x7
//  L2: ->16x6x6  L3: ->16x3x3  L4: ->16x1x1 (T=64)  L5: ->10 (T=16)
//  bit=1 <=> +1 ; out bit = (#mismatch >= T/2).

#define NTHREADS 256
#define NWARPS 8
#define IMGS_PER_WARP 8
#define IMGS_PER_BLOCK 64
#define WPW 196                        // sbits words per warp
#define NWORDS (NWARPS * WPW)          // 1568
#define S1 53
#define S2 37
#define S3 13
#define FULL 0xFFFFFFFFu

// 16-oc XNOR-popcount NAND step; W read per-use from shared (broadcast).
__device__ __forceinline__ uint32_t nand16(uint64_t a, const uint64_t* Wsh) {
    const uint32_t al = (uint32_t)a, ah = (uint32_t)(a >> 32);
    uint32_t acc = 0;
#pragma unroll
    for (int oc = 0; oc < 16; oc++) {
        const uint64_t w = Wsh[oc];          // LDS.64, uniform -> broadcast
        uint32_t xl = al ^ (uint32_t)w;
        uint32_t xh = ah ^ (uint32_t)(w >> 32);
        uint32_t D = __popc(xl) + __popc(xh) + 32;
        acc |= (D >> 6) << oc;               // 1 iff mismatches >= 32
    }
    return acc;
}

// L0 cell: 2x2 patch (rows rA,rB, cols cc,cc+1) vs all 16 channels at once.
__device__ __forceinline__ uint32_t cell16(uint32_t rA, uint32_t rB, int cc,
                                           uint32_t W00, uint32_t W01,
                                           uint32_t W02, uint32_t W03) {
    uint32_t m0 = W00 ^ (uint32_t)(((int)(rA << (31 - cc))) >> 31);
    uint32_t m1 = W01 ^ (uint32_t)(((int)(rA << (30 - cc))) >> 31);
    uint32_t m2 = W02 ^ (uint32_t)(((int)(rB << (31 - cc))) >> 31);
    uint32_t m3 = W03 ^ (uint32_t)(((int)(rB << (30 - cc))) >> 31);
    return (m0 & m1) | (m2 & m3) | ((m0 ^ m1) & (m2 ^ m3));
}

__global__ void __launch_bounds__(NTHREADS, 4)
bnn_mnist_kernel(const float* __restrict__ x,
                 const float* __restrict__ w0, const float* __restrict__ w1,
                 const float* __restrict__ w2, const float* __restrict__ w3,
                 const float* __restrict__ w4, const float* __restrict__ w5,
                 float* __restrict__ out, int B)
{
    __shared__ uint32_t sbits[NWORDS + 1];
    __shared__ uint64_t sw_sh[4][16];
    __shared__ uint32_t sw0t[4];
    __shared__ uint32_t sw5s[10];
    __shared__ uint32_t sact1[IMGS_PER_BLOCK * S1];
    __shared__ uint32_t sact2[IMGS_PER_BLOCK * S2];
    __shared__ uint32_t sact3[IMGS_PER_BLOCK * S3];

    const int tid  = threadIdx.x;
    const int lane = tid & 31;
    const int warp = tid >> 5;
    const int b0 = blockIdx.x * IMGS_PER_BLOCK;

    // ---- weight prep ----
    if (tid < 64) {
        int L = tid >> 4, oc = tid & 15;
        const float* wp = (L == 0 ? w1 : L == 1 ? w2 : L == 2 ? w3 : w4) + oc * 64;
        uint64_t v = 0;
#pragma unroll
        for (int ic = 0; ic < 16; ic++)
#pragma unroll
            for (int tap = 0; tap < 4; tap++)
                if (wp[ic * 4 + tap] > 0.0f) v |= 1ull << (tap * 16 + ic);
        sw_sh[L][oc] = v;
    } else if (tid < 68) {
        int k = tid - 64;
        uint32_t v = 0;
#pragma unroll
        for (int c = 0; c < 16; c++)
            if (w0[c * 4 + k] > 0.0f) v |= 1u << c;
        sw0t[k] = v;
    } else if (tid < 78) {
        int c = tid - 68;
        uint32_t v = 0;
#pragma unroll
        for (int ic = 0; ic < 16; ic++)
            if (w5[c * 16 + ic] > 0.0f) v |= 1u << ic;
        sw5s[c] = v;
    } else if (tid == 78) {
        sbits[NWORDS] = 0;
    }
    __syncthreads();

    // ---- warp-autonomous load + binarize + pack (8 images/warp, MLP-7) ----
    {
        const float* chunk = x + (size_t)b0 * 784 + warp * (IMGS_PER_WARP * 784);
        const int sb = warp * WPW;
        if (b0 + IMGS_PER_BLOCK <= B) {
            const float4* c4 = (const float4*)chunk;
#pragma unroll
            for (int c0 = 0; c0 < 49; c0 += 7) {
                float4 v[7];
#pragma unroll
                for (int u = 0; u < 7; u++)
                    v[u] = c4[(c0 + u) * 32 + lane];
#pragma unroll
                for (int u = 0; u < 7; u++) {
                    uint32_t nib = (uint32_t)(v[u].x > 0.0f) | ((uint32_t)(v[u].y > 0.0f) << 1)
                                 | ((uint32_t)(v[u].z > 0.0f) << 2) | ((uint32_t)(v[u].w > 0.0f) << 3);
                    uint32_t val = nib << (4 * (lane & 7));
                    val |= __shfl_xor_sync(FULL, val, 1);
                    val |= __shfl_xor_sync(FULL, val, 2);
                    val |= __shfl_xor_sync(FULL, val, 4);
                    if ((lane & 7) == 0) sbits[sb + (c0 + u) * 4 + (lane >> 3)] = val;
                }
            }
        } else {
            const int nfl = max(min(IMGS_PER_BLOCK, B - b0), 0) * 784 - warp * (IMGS_PER_WARP * 784);
            for (int wdx = 0; wdx < WPW; wdx++) {
                int f = wdx * 32 + lane;
                float v = (f < nfl) ? chunk[f] : 0.0f;
                unsigned bb = __ballot_sync(FULL, v > 0.0f);
                if (lane == 0) sbits[sb + wdx] = bb;
            }
        }
    }
    __syncwarp();

    const int sub  = tid & 3;
    const int limg = tid >> 2;
    const int img  = b0 + limg;
    const int bitbase = limg * 784;
    const int row1 = limg * S1;
    const int row2 = limg * S2;
    const int row3 = limg * S3;

    const uint32_t W00 = sw0t[0], W01 = sw0t[1], W02 = sw0t[2], W03 = sw0t[3];

    // ---- L0+L1: rows dealt {0,4},{1,5},{2,6},{3} ----
#pragma unroll
    for (int t = 0; t < 2; t++) {
        const int i = sub + 4 * t;
        if (i < 7) {
            const int r0 = bitbase + 112 * i;
            int bp = r0;
            uint32_t rA0 = __funnelshift_r(sbits[bp >> 5], sbits[(bp >> 5) + 1], bp);
            bp = r0 + 28;
            uint32_t rB0 = __funnelshift_r(sbits[bp >> 5], sbits[(bp >> 5) + 1], bp);
            bp = r0 + 56;
            uint32_t rA1 = __funnelshift_r(sbits[bp >> 5], sbits[(bp >> 5) + 1], bp);
            bp = r0 + 84;
            uint32_t rB1 = __funnelshift_r(sbits[bp >> 5], sbits[(bp >> 5) + 1], bp);
#pragma unroll
            for (int j = 0; j < 7; j++) {
                const int cc = 4 * j;
                uint32_t v00 = cell16(rA0, rB0, cc,     W00, W01, W02, W03) & 0xFFFFu;
                uint32_t v01 = cell16(rA0, rB0, cc + 2, W00, W01, W02, W03) & 0xFFFFu;
                uint32_t v10 = cell16(rA1, rB1, cc,     W00, W01, W02, W03) & 0xFFFFu;
                uint32_t v11 = cell16(rA1, rB1, cc + 2, W00, W01, W02, W03) & 0xFFFFu;
                uint64_t a64 = (uint64_t)(v00 | (v01 << 16))
                             | ((uint64_t)(v10 | (v11 << 16)) << 32);
                sact1[row1 + i * 7 + j] = nand16(a64, sw_sh[0]);
            }
        }
    }
    __syncwarp();

    // ---- L2: 7x7 -> 6x6; p = sub + 4k (exact cover of 36) ----
#pragma unroll
    for (int k = 0; k < 9; k++) {
        const int p = sub + 4 * k;
        const int i = p / 6;
        const int q = row1 + p + i;
        uint64_t a64 = (uint64_t)sact1[q] | ((uint64_t)sact1[q + 1] << 16)
                     | ((uint64_t)sact1[q + 7] << 32) | ((uint64_t)sact1[q + 8] << 48);
        sact2[row2 + p] = nand16(a64, sw_sh[1]);
    }
    __syncwarp();

    // ---- L3: 6x6 -> 3x3; p = sub + 4k, guard p<9 ----
#pragma unroll
    for (int k = 0; k < 3; k++) {
        const int p = sub + 4 * k;
        if (p < 9) {
            const int i = p / 3;
            const int j = p - 3 * i;
            const int q = row2 + 12 * i + 2 * j;
            uint64_t a64 = (uint64_t)sact2[q] | ((uint64_t)sact2[q + 1] << 16)
                         | ((uint64_t)sact2[q + 6] << 32) | ((uint64_t)sact2[q + 7] << 48);
            sact3[row3 + p] = nand16(a64, sw_sh[2]);
        }
    }
    __syncwarp();

    // ---- L4: 4 ocs per sub, merge via shfl_xor OR (subs are adjacent lanes) ----
    uint32_t act4;
    {
        uint64_t a4 = (uint64_t)sact3[row3 + 0] | ((uint64_t)sact3[row3 + 1] << 16)
                    | ((uint64_t)sact3[row3 + 3] << 32) | ((uint64_t)sact3[row3 + 4] << 48);
        uint32_t acc = 0;
#pragma unroll
        for (int m = 0; m < 4; m++) {
            const int oc = sub * 4 + m;
            uint64_t xx = a4 ^ sw_sh[3][oc];
            uint32_t D = __popc((uint32_t)xx) + __popc((uint32_t)(xx >> 32)) + 32;
            acc |= (D >> 6) << oc;
        }
        acc |= __shfl_xor_sync(FULL, acc, 1);
        acc |= __shfl_xor_sync(FULL, acc, 2);
        act4 = acc;
    }

    // ---- L5: classes dealt per sub ----
    if (img < B) {
        float* o = out + (size_t)img * 10;
#pragma unroll
        for (int k = 0; k < 3; k++) {
            const int oc = sub + 4 * k;
            if (oc < 10) {
                uint32_t D = __popc((act4 ^ sw5s[oc]) & 0xFFFFu);
                o[oc] = (D >= 8) ? 1.0f : -1.0f;
            }
        }
    }
}

extern "C" void kernel_launch(void* const* d_in, const int* in_sizes, int n_in,
                              void* d_out, int out_size)
{
    const float* x  = (const float*)d_in[0];
    const float* w0 = (const float*)d_in[1];
    const float* w1 = (const float*)d_in[2];
    const float* w2 = (const float*)d_in[3];
    const float* w3 = (const float*)d_in[4];
    const float* w4 = (const float*)d_in[5];
    const float* w5 = (const float*)d_in[6];
    float* out = (float*)d_out;

    int B = in_sizes[0] / 784;
    int grid = (B + IMGS_PER_BLOCK - 1) / IMGS_PER_BLOCK;
    bnn_mnist_kernel<<<grid, NTHREADS>>>(x, w0, w1, w2, w3, w4, w5, out, B);
}

// round 15
// speedup vs baseline: 1.5865x; 1.1261x over previous
#include <cuda_runtime.h>
#include <cstdint>

// Binarized NAND-conv net. Warp-autonomous (8 images/warp), 4 threads/image,
// 256-thread blocks, register-resident weights (proven best config, R9).
// CHANGE vs R9: load phase uses strided LDG.32 + __ballot_sync -> sbits words
// produced directly in bit order with ZERO shuffles (no 3-deep SHFL chains).
//  L0: 1x28x28 ->16x14x14 (T=4, arithmetic 2-of-4 majority)  L1: ->16x7x7
//  L2: ->16x6x6  L3: ->16x3x3  L4: ->16x1x1 (T=64)  L5: ->10 (T=16)
//  bit=1 <=> +1 ; out bit = (#mismatch >= T/2).

#define NTHREADS 256
#define NWARPS 8
#define IMGS_PER_WARP 8
#define IMGS_PER_BLOCK 64
#define WPW 196                        // sbits words per warp
#define NWORDS (NWARPS * WPW)          // 1568
#define S1 53
#define S2 37
#define S3 13
#define FULL 0xFFFFFFFFu

__device__ __forceinline__ uint32_t nand16(uint64_t a, const uint64_t (&W)[16]) {
    const uint32_t al = (uint32_t)a, ah = (uint32_t)(a >> 32);
    uint32_t acc = 0;
#pragma unroll
    for (int oc = 0; oc < 16; oc++) {
        uint32_t xl = al ^ (uint32_t)W[oc];
        uint32_t xh = ah ^ (uint32_t)(W[oc] >> 32);
        uint32_t D = __popc(xl) + __popc(xh) + 32;
        acc |= (D >> 6) << oc;        // 1 iff mismatches >= 32 (D in [32,96])
    }
    return acc;
}

// L0 cell: 2x2 patch (rows rA,rB, cols cc,cc+1) vs all 16 channels at once.
__device__ __forceinline__ uint32_t cell16(uint32_t rA, uint32_t rB, int cc,
                                           uint32_t W00, uint32_t W01,
                                           uint32_t W02, uint32_t W03) {
    uint32_t m0 = W00 ^ (uint32_t)(((int)(rA << (31 - cc))) >> 31);
    uint32_t m1 = W01 ^ (uint32_t)(((int)(rA << (30 - cc))) >> 31);
    uint32_t m2 = W02 ^ (uint32_t)(((int)(rB << (31 - cc))) >> 31);
    uint32_t m3 = W03 ^ (uint32_t)(((int)(rB << (30 - cc))) >> 31);
    return (m0 & m1) | (m2 & m3) | ((m0 ^ m1) & (m2 ^ m3));
}

__global__ void __launch_bounds__(NTHREADS, 3)
bnn_mnist_kernel(const float* __restrict__ x,
                 const float* __restrict__ w0, const float* __restrict__ w1,
                 const float* __restrict__ w2, const float* __restrict__ w3,
                 const float* __restrict__ w4, const float* __restrict__ w5,
                 float* __restrict__ out, int B)
{
    __shared__ uint32_t sbits[NWORDS + 1];
    __shared__ uint64_t sw_sh[4][16];
    __shared__ uint32_t sw0t[4];
    __shared__ uint32_t sw5s[10];
    __shared__ uint32_t sact1[IMGS_PER_BLOCK * S1];
    __shared__ uint32_t sact2[IMGS_PER_BLOCK * S2];
    __shared__ uint32_t sact3[IMGS_PER_BLOCK * S3];

    const int tid  = threadIdx.x;
    const int lane = tid & 31;
    const int warp = tid >> 5;
    const int b0 = blockIdx.x * IMGS_PER_BLOCK;

    // ---- weight prep ----
    if (tid < 64) {
        int L = tid >> 4, oc = tid & 15;
        const float* wp = (L == 0 ? w1 : L == 1 ? w2 : L == 2 ? w3 : w4) + oc * 64;
        uint64_t v = 0;
#pragma unroll
        for (int ic = 0; ic < 16; ic++)
#pragma unroll
            for (int tap = 0; tap < 4; tap++)
                if (wp[ic * 4 + tap] > 0.0f) v |= 1ull << (tap * 16 + ic);
        sw_sh[L][oc] = v;
    } else if (tid < 68) {
        int k = tid - 64;
        uint32_t v = 0;
#pragma unroll
        for (int c = 0; c < 16; c++)
            if (w0[c * 4 + k] > 0.0f) v |= 1u << c;
        sw0t[k] = v;
    } else if (tid < 78) {
        int c = tid - 68;
        uint32_t v = 0;
#pragma unroll
        for (int ic = 0; ic < 16; ic++)
            if (w5[c * 16 + ic] > 0.0f) v |= 1u << ic;
        sw5s[c] = v;
    } else if (tid == 78) {
        sbits[NWORDS] = 0;
    }
    __syncthreads();

    // ---- warp-autonomous load + binarize: strided LDG.32 + ballot ----
    // Chunk c covers floats [128c, 128c+128) of this warp's 8 images.
    // Load q (q=0..3): lane l reads float 128c+32q+l  -> ballot = word 4c+q,
    // bit l = (float[32*(4c+q)+l] > 0). Coalesced, zero shuffles.
    {
        const float* chunk = x + (size_t)b0 * 784 + warp * (IMGS_PER_WARP * 784);
        const int sb = warp * WPW;
        if (b0 + IMGS_PER_BLOCK <= B) {
#pragma unroll
            for (int c0 = 0; c0 < 49; c0 += 7) {
                float v[28];
#pragma unroll
                for (int u = 0; u < 7; u++)
#pragma unroll
                    for (int q = 0; q < 4; q++)
                        v[u * 4 + q] = chunk[(c0 + u) * 128 + q * 32 + lane];
#pragma unroll
                for (int u = 0; u < 7; u++)
#pragma unroll
                    for (int q = 0; q < 4; q++) {
                        unsigned bal = __ballot_sync(FULL, v[u * 4 + q] > 0.0f);
                        if (lane == q) sbits[sb + (c0 + u) * 4 + q] = bal;
                    }
            }
        } else {
            const int nfl = max(min(IMGS_PER_BLOCK, B - b0), 0) * 784 - warp * (IMGS_PER_WARP * 784);
            for (int wdx = 0; wdx < WPW; wdx++) {
                int f = wdx * 32 + lane;
                float v = (f < nfl) ? chunk[f] : 0.0f;
                unsigned bb = __ballot_sync(FULL, v > 0.0f);
                if (lane == 0) sbits[sb + wdx] = bb;
            }
        }
    }
    __syncwarp();

    const int sub  = tid & 3;
    const int limg = tid >> 2;
    const int img  = b0 + limg;
    const int bitbase = limg * 784;
    const int row1 = limg * S1;
    const int row2 = limg * S2;
    const int row3 = limg * S3;

    const uint32_t W00 = sw0t[0], W01 = sw0t[1], W02 = sw0t[2], W03 = sw0t[3];

    uint64_t W[16];

    // ---- L0+L1: rows dealt {0,4},{1,5},{2,6},{3} ----
#pragma unroll
    for (int k = 0; k < 16; k++) W[k] = sw_sh[0][k];
#pragma unroll
    for (int t = 0; t < 2; t++) {
        const int i = sub + 4 * t;
        if (i < 7) {
            const int r0 = bitbase + 112 * i;
            int bp = r0;
            uint32_t rA0 = __funnelshift_r(sbits[bp >> 5], sbits[(bp >> 5) + 1], bp);
            bp = r0 + 28;
            uint32_t rB0 = __funnelshift_r(sbits[bp >> 5], sbits[(bp >> 5) + 1], bp);
            bp = r0 + 56;
            uint32_t rA1 = __funnelshift_r(sbits[bp >> 5], sbits[(bp >> 5) + 1], bp);
            bp = r0 + 84;
            uint32_t rB1 = __funnelshift_r(sbits[bp >> 5], sbits[(bp >> 5) + 1], bp);
#pragma unroll
            for (int j = 0; j < 7; j++) {
                const int cc = 4 * j;
                uint32_t v00 = cell16(rA0, rB0, cc,     W00, W01, W02, W03) & 0xFFFFu;
                uint32_t v01 = cell16(rA0, rB0, cc + 2, W00, W01, W02, W03) & 0xFFFFu;
                uint32_t v10 = cell16(rA1, rB1, cc,     W00, W01, W02, W03) & 0xFFFFu;
                uint32_t v11 = cell16(rA1, rB1, cc + 2, W00, W01, W02, W03) & 0xFFFFu;
                uint64_t a64 = (uint64_t)(v00 | (v01 << 16))
                             | ((uint64_t)(v10 | (v11 << 16)) << 32);
                sact1[row1 + i * 7 + j] = nand16(a64, W);
            }
        }
    }
    __syncwarp();

    // ---- L2: 7x7 -> 6x6; p = sub + 4k (exact cover of 36) ----
#pragma unroll
    for (int k = 0; k < 16; k++) W[k] = sw_sh[1][k];
#pragma unroll
    for (int k = 0; k < 9; k++) {
        const int p = sub + 4 * k;
        const int i = p / 6;
        const int q = row1 + p + i;
        uint64_t a64 = (uint64_t)sact1[q] | ((uint64_t)sact1[q + 1] << 16)
                     | ((uint64_t)sact1[q + 7] << 32) | ((uint64_t)sact1[q + 8] << 48);
        sact2[row2 + p] = nand16(a64, W);
    }
    __syncwarp();

    // ---- L3: 6x6 -> 3x3; p = sub + 4k, guard p<9 ----
#pragma unroll
    for (int k = 0; k < 16; k++) W[k] = sw_sh[2][k];
#pragma unroll
    for (int k = 0; k < 3; k++) {
        const int p = sub + 4 * k;
        if (p < 9) {
            const int i = p / 3;
            const int j = p - 3 * i;
            const int q = row2 + 12 * i + 2 * j;
            uint64_t a64 = (uint64_t)sact2[q] | ((uint64_t)sact2[q + 1] << 16)
                         | ((uint64_t)sact2[q + 6] << 32) | ((uint64_t)sact2[q + 7] << 48);
            sact3[row3 + p] = nand16(a64, W);
        }
    }
    __syncwarp();

    // ---- L4: 4 ocs per sub, merge via shfl_xor OR ----
    uint32_t act4;
    {
        uint64_t a4 = (uint64_t)sact3[row3 + 0] | ((uint64_t)sact3[row3 + 1] << 16)
                    | ((uint64_t)sact3[row3 + 3] << 32) | ((uint64_t)sact3[row3 + 4] << 48);
        uint32_t acc = 0;
#pragma unroll
        for (int m = 0; m < 4; m++) {
            const int oc = sub * 4 + m;
            uint64_t xx = a4 ^ sw_sh[3][oc];
            uint32_t D = __popc((uint32_t)xx) + __popc((uint32_t)(xx >> 32)) + 32;
            acc |= (D >> 6) << oc;
        }
        acc |= __shfl_xor_sync(FULL, acc, 1);
        acc |= __shfl_xor_sync(FULL, acc, 2);
        act4 = acc;
    }

    // ---- L5: classes dealt per sub ----
    if (img < B) {
        float* o = out + (size_t)img * 10;
#pragma unroll
        for (int k = 0; k < 3; k++) {
            const int oc = sub + 4 * k;
            if (oc < 10) {
                uint32_t D = __popc((act4 ^ sw5s[oc]) & 0xFFFFu);
                o[oc] = (D >= 8) ? 1.0f : -1.0f;
            }
        }
    }
}

extern "C" void kernel_launch(void* const* d_in, const int* in_sizes, int n_in,
                              void* d_out, int out_size)
{
    const float* x  = (const float*)d_in[0];
    const float* w0 = (const float*)d_in[1];
    const float* w1 = (const float*)d_in[2];
    const float* w2 = (const float*)d_in[3];
    const float* w3 = (const float*)d_in[4];
    const float* w4 = (const float*)d_in[5];
    const float* w5 = (const float*)d_in[6];
    float* out = (float*)d_out;

    int B = in_sizes[0] / 784;
    int grid = (B + IMGS_PER_BLOCK - 1) / IMGS_PER_BLOCK;
    bnn_mnist_kernel<<<grid, NTHREADS>>>(x, w0, w1, w2, w3, w4, w5, out, B);
}